// round 16
// baseline (speedup 1.0000x reference)
#include <cuda_runtime.h>
#include <cuda_fp16.h>
#include <cstdint>

// ---------------- problem shapes ----------------
constexpr int NBR = 32;
constexpr int CC  = 384;
constexpr int CZ  = 128;
constexpr int NPC = 4;            // (b,n) pairs per CTA
constexpr int ROWS = NPC * NBR;   // 128 = M
constexpr int BN = 4096;
constexpr int THREADS = 256;      // 8 warps = 2 groups x 4

// transposed fp16 weights: [d][k]
__device__ __half g_WsT[CC * CC];
__device__ __half g_WzT[CC * CZ];

// ---------------- smem layout (bytes) ----------------
constexpr uint32_t OFF_A  = 0;                       // 128 x 784B
constexpr uint32_t OFF_Z  = 100352;                  // 128 x 272B
constexpr uint32_t OFF_W  = 135168;                  // 2 grp x 2 buf x 17408
constexpr uint32_t OFF_SI = 204800;                  // 4x384 fp32
constexpr uint32_t OFF_SN = 210944;                  // 4x384 fp32
constexpr uint32_t OFF_M  = 217088;                  // 128 fp32
constexpr uint32_t SMEM_TOTAL = 217600;

constexpr int SA = 784;    // A row stride bytes
constexpr int SZ = 272;    // Z row stride bytes
constexpr int SW = 272;    // W row stride bytes
constexpr uint32_t WBUF = 17408;     // one buf: 64 rows x 272B
constexpr uint32_t WGRP = 34816;     // per-group region (2 bufs)

// ---------------- asm helpers ----------------
__device__ __forceinline__ uint32_t smem_u32(const void* p) {
    uint32_t a;
    asm("{ .reg .u64 t; cvta.to.shared.u64 t, %1; cvt.u32.u64 %0, t; }" : "=r"(a) : "l"(p));
    return a;
}
__device__ __forceinline__ void ldsm4(uint32_t& r0, uint32_t& r1, uint32_t& r2, uint32_t& r3,
                                      uint32_t addr) {
    asm volatile("ldmatrix.sync.aligned.m8n8.x4.shared.b16 {%0,%1,%2,%3}, [%4];"
                 : "=r"(r0), "=r"(r1), "=r"(r2), "=r"(r3) : "r"(addr));
}
__device__ __forceinline__ void mma16816(float* c, const uint32_t* a, const uint32_t* b) {
    asm volatile("mma.sync.aligned.m16n8k16.row.col.f32.f16.f16.f32 "
                 "{%0,%1,%2,%3}, {%4,%5,%6,%7}, {%8,%9}, {%0,%1,%2,%3};"
                 : "+f"(c[0]), "+f"(c[1]), "+f"(c[2]), "+f"(c[3])
                 : "r"(a[0]), "r"(a[1]), "r"(a[2]), "r"(a[3]), "r"(b[0]), "r"(b[1]));
}
__device__ __forceinline__ void cp16(uint32_t dst, const void* src) {
    asm volatile("cp.async.cg.shared.global [%0], [%1], 16;" :: "r"(dst), "l"(src));
}
__device__ __forceinline__ void bar_grp(int id) {
    asm volatile("bar.sync %0, 128;" :: "r"(id) : "memory");
}

// ---------------- weight fp32 -> fp16 transpose ----------------
__global__ void convert_w_t(const float* __restrict__ Ws, const float* __restrict__ Wz) {
    int i = blockIdx.x * blockDim.x + threadIdx.x;
    if (i < CC * CC) {
        int d = i / CC, k = i % CC;
        g_WsT[i] = __float2half_rn(Ws[k * CC + d]);
    }
    if (i < CC * CZ) {
        int d = i / CZ, k = i % CZ;
        g_WzT[i] = __float2half_rn(Wz[k * CC + d]);
    }
}

// ---------------- W staging: group grp loads its 64-row slice of stage s ----------------
__device__ __forceinline__ void issue_w_load(int s, int grp, uint32_t dstBase, int gtid) {
    const int sub = s & 3, d0 = (s >> 2) * 128;
    const __half* src;
    int rstride;
    if (sub == 0) { src = g_WzT + (size_t)(d0 + grp * 64) * CZ; rstride = CZ; }
    else          { src = g_WsT + (size_t)(d0 + grp * 64) * CC + (sub - 1) * 128; rstride = CC; }
    #pragma unroll
    for (int i = 0; i < 8; i++) {
        int idx = gtid + i * 128;          // 0..1023 : 64 rows x 16 int4
        int r = idx >> 4, c = idx & 15;
        cp16(dstBase + r * SW + c * 16, src + (size_t)r * rstride + c * 8);
    }
    asm volatile("cp.async.commit_group;");
}

// ---------------- one GEMM stage: acc += A(32m x 128k) @ W(64n x 128k)^T ----------------
__device__ __forceinline__ void gemm_stage(uint32_t aLane, int aMfStride, uint32_t wLane,
                                           float (&acc)[2][8][4], bool zero) {
    if (zero) {
        #pragma unroll
        for (int mf = 0; mf < 2; mf++)
            #pragma unroll
            for (int nf = 0; nf < 8; nf++)
                #pragma unroll
                for (int e = 0; e < 4; e++) acc[mf][nf][e] = 0.f;
    }
    #pragma unroll
    for (int k = 0; k < 8; k++) {
        uint32_t a[2][4];
        #pragma unroll
        for (int mf = 0; mf < 2; mf++)
            ldsm4(a[mf][0], a[mf][1], a[mf][2], a[mf][3], aLane + mf * aMfStride + k * 32);
        uint32_t b[8][2];
        #pragma unroll
        for (int fp = 0; fp < 4; fp++) {
            uint32_t r0, r1, r2, r3;
            ldsm4(r0, r1, r2, r3, wLane + fp * (16 * SW) + k * 32);
            b[2 * fp][0] = r0; b[2 * fp][1] = r1;
            b[2 * fp + 1][0] = r2; b[2 * fp + 1][1] = r3;
        }
        #pragma unroll
        for (int mf = 0; mf < 2; mf++)
            #pragma unroll
            for (int nf = 0; nf < 8; nf++)
                mma16816(acc[mf][nf], a[mf], b[nf]);
    }
}

// ---------------- fused main kernel ----------------
__global__ void __launch_bounds__(THREADS, 1) fused_kernel(
    const float* __restrict__ s_i,
    const float* __restrict__ s_ij,
    const float* __restrict__ m_ij,
    const float* __restrict__ z_ij,
    const float* __restrict__ gamma,
    const float* __restrict__ beta,
    float* __restrict__ out)
{
    extern __shared__ char smem[];
    const uint32_t sb = smem_u32(smem);
    const int tid = threadIdx.x, warp = tid >> 5, lane = tid & 31;
    const int grp = warp >> 2;            // pipeline group 0/1 (owns 64 output cols)
    const int wm = warp & 3;              // 4 m-positions; each warp: 32m x 64n
    const int gtid = tid & 127;
    const int bn0 = blockIdx.x * NPC;
    const uint32_t wgbase = sb + OFF_W + (uint32_t)grp * WGRP;

    // ---- prefetch this group's W stages 0 and 1
    issue_w_load(0, grp, wgbase, gtid);
    issue_w_load(1, grp, wgbase + WBUF, gtid);

    // ---- load & convert Z = z_ij (128 x 128), shared by both groups
    {
        const float4* g = (const float4*)(z_ij + (size_t)bn0 * NBR * CZ);
        #pragma unroll
        for (int i = 0; i < 8; i++) {
            int idx = tid + i * THREADS;
            int r = idx >> 4, c = idx & 15;
            float4 v0 = g[r * 32 + c * 2];
            float4 v1 = g[r * 32 + c * 2 + 1];
            __half2 h0 = __floats2half2_rn(v0.x, v0.y), h1 = __floats2half2_rn(v0.z, v0.w);
            __half2 h2 = __floats2half2_rn(v1.x, v1.y), h3 = __floats2half2_rn(v1.z, v1.w);
            uint4 u;
            u.x = *(uint32_t*)&h0; u.y = *(uint32_t*)&h1;
            u.z = *(uint32_t*)&h2; u.w = *(uint32_t*)&h3;
            *(uint4*)(smem + OFF_Z + r * SZ + c * 16) = u;
        }
    }
    // ---- s_i, mask  (looped SI load — 384 float4 > 256 threads)
    {
        const float4* g = (const float4*)(s_i + (size_t)bn0 * CC);
        float4* d = (float4*)(smem + OFF_SI);
        for (int idx = tid; idx < NPC * CC / 4; idx += THREADS) d[idx] = g[idx];
        if (tid < ROWS) ((float*)(smem + OFF_M))[tid] = m_ij[(size_t)bn0 * NBR + tid];
    }
    asm volatile("cp.async.wait_group 0;" ::: "memory");   // W0, W1 resident (this grp)
    __syncthreads();                                       // Z / si / mask visible

    // ---- lane-resolved base addresses
    const uint32_t aA = sb + OFF_A + (32 * wm + (lane & 15)) * SA + (lane >> 4) * 16;
    const uint32_t aZ = sb + OFF_Z + (32 * wm + (lane & 15)) * SZ + (lane >> 4) * 16;
    const int g8 = lane >> 3;
    const uint32_t wOfs = (uint32_t)(((g8 >> 1) * 8 + (lane & 7)) * SW + (g8 & 1) * 16);

    float cG[2][8][4], cP[2][8][4];

    const float* M_s  = (const float*)(smem + OFF_M);
    const float* SI_s = (const float*)(smem + OFF_SI);
    float*       SN_s = (float*)(smem + OFF_SN);
    const float mv00 = M_s[32 * wm + (lane >> 2)];
    const float mv01 = M_s[32 * wm + (lane >> 2) + 8];
    const float mv10 = M_s[32 * wm + 16 + (lane >> 2)];
    const float mv11 = M_s[32 * wm + 16 + (lane >> 2) + 8];

    // ==== phase B: per-warp A-convert slice, then GEMM2 stage 0 — no barrier between,
    //      so A-load latency hides under other warps' MMA issue.
    {
        const float4* g = (const float4*)(s_ij + (size_t)bn0 * NBR * CC);
        #pragma unroll
        for (int j = 0; j < 24; j++) {
            int idx = warp * 768 + j * 32 + lane;   // this warp: rows [16*warp, 16*warp+16)
            int r = idx / 48, gcol = idx % 48;
            float4 v0 = g[r * 96 + gcol * 2];
            float4 v1 = g[r * 96 + gcol * 2 + 1];
            __half2 h0 = __floats2half2_rn(v0.x, v0.y), h1 = __floats2half2_rn(v0.z, v0.w);
            __half2 h2 = __floats2half2_rn(v1.x, v1.y), h3 = __floats2half2_rn(v1.z, v1.w);
            uint4 u;
            u.x = *(uint32_t*)&h0; u.y = *(uint32_t*)&h1;
            u.z = *(uint32_t*)&h2; u.w = *(uint32_t*)&h3;
            *(uint4*)(smem + OFF_A + r * SA + gcol * 16) = u;
        }
        gemm_stage(aZ, 16 * SZ, wgbase + wOfs, cG, true);   // stage 0 (Wz slice, dt=0)
    }
    __syncthreads();                          // A complete everywhere; buf0 free (both grps)
    issue_w_load(2, grp, wgbase, gtid);       // stage 2 -> this group's buf0

    // ==== stages 1..11 — each group pipelines independently (named barriers)
    for (int s = 1; s < 12; ++s) {
        const int sub = s & 3, dt = s >> 2;
        const uint32_t wbuf = wgbase + (uint32_t)(s & 1) * WBUF + wOfs;

        if (sub == 0) gemm_stage(aZ, 16 * SZ, wbuf, cG, true);
        else          gemm_stage(aA + (sub - 1) * 256, 16 * SA, wbuf, cP, sub == 1);

        if (sub == 3) {
            // epilogue: msg = m*(P - s_i)*G, reduce over this warp's 32 neighbor rows
            const int d0 = dt * 128;
            #pragma unroll
            for (int nf = 0; nf < 8; nf++) {
                const int col0 = d0 + grp * 64 + nf * 8 + (lane & 3) * 2;
                const float si0 = SI_s[wm * CC + col0];
                const float si1 = SI_s[wm * CC + col0 + 1];
                float t0 = mv00 * (cP[0][nf][0] - si0) * cG[0][nf][0]
                         + mv01 * (cP[0][nf][2] - si0) * cG[0][nf][2]
                         + mv10 * (cP[1][nf][0] - si0) * cG[1][nf][0]
                         + mv11 * (cP[1][nf][2] - si0) * cG[1][nf][2];
                float t1 = mv00 * (cP[0][nf][1] - si1) * cG[0][nf][1]
                         + mv01 * (cP[0][nf][3] - si1) * cG[0][nf][3]
                         + mv10 * (cP[1][nf][1] - si1) * cG[1][nf][1]
                         + mv11 * (cP[1][nf][3] - si1) * cG[1][nf][3];
                #pragma unroll
                for (int o = 4; o <= 16; o <<= 1) {
                    t0 += __shfl_xor_sync(0xffffffffu, t0, o);
                    t1 += __shfl_xor_sync(0xffffffffu, t1, o);
                }
                if ((lane >> 2) == 0) {
                    SN_s[wm * CC + col0]     = t0;
                    SN_s[wm * CC + col0 + 1] = t1;
                }
            }
        }
        bar_grp(1 + grp);                      // this group done with buf(s&1)
        if (s + 2 < 12) issue_w_load(s + 2, grp, wgbase + (uint32_t)(s & 1) * WBUF, gtid);
        if (s + 1 < 12) {
            if (s + 2 < 12) asm volatile("cp.async.wait_group 1;" ::: "memory");
            else            asm volatile("cp.async.wait_group 0;" ::: "memory");
            bar_grp(1 + grp);                  // stage s+1 visible to this group
        }
    }

    // ---- fused layernorm: needs SN from both groups
    __syncthreads();
    if (warp < 4) {
        const float* x = SN_s + warp * CC;
        float v[12], sm = 0.f, sq = 0.f;
        #pragma unroll
        for (int j = 0; j < 12; j++) {
            v[j] = x[lane + j * 32];
            sm += v[j]; sq += v[j] * v[j];
        }
        #pragma unroll
        for (int o = 16; o; o >>= 1) {
            sm += __shfl_xor_sync(0xffffffffu, sm, o);
            sq += __shfl_xor_sync(0xffffffffu, sq, o);
        }
        const float mu = sm * (1.0f / CC);
        const float var = sq * (1.0f / CC) - mu * mu;
        const float rstd = rsqrtf(var + 1e-6f);
        float* o_ = out + (size_t)(bn0 + warp) * CC;
        #pragma unroll
        for (int j = 0; j < 12; j++) {
            int e = lane + j * 32;
            o_[e] = (v[j] - mu) * rstd * gamma[e] + beta[e];
        }
    }
}

// ---------------- launch ----------------
extern "C" void kernel_launch(void* const* d_in, const int* in_sizes, int n_in,
                              void* d_out, int out_size)
{
    const float* s_i   = (const float*)d_in[0];
    const float* s_ij  = (const float*)d_in[1];
    const float* m_ij  = (const float*)d_in[2];
    const float* z_ij  = (const float*)d_in[3];
    const float* W_s   = (const float*)d_in[4];
    const float* W_z   = (const float*)d_in[5];
    const float* gamma = (const float*)d_in[6];
    const float* beta  = (const float*)d_in[7];
    float* out = (float*)d_out;

    cudaFuncSetAttribute(fused_kernel, cudaFuncAttributeMaxDynamicSharedMemorySize,
                         (int)SMEM_TOTAL);

    convert_w_t<<<(CC * CC + 255) / 256, 256>>>(W_s, W_z);
    fused_kernel<<<BN / NPC, THREADS, SMEM_TOTAL>>>(s_i, s_ij, m_ij, z_ij, gamma, beta, out);
}